// round 15
// baseline (speedup 1.0000x reference)
#include <cuda_runtime.h>
#include <math.h>

// Problem dims
#define BB   256
#define TT   1024
#define FF   64
#define EE   256
#define GG   1024      // 4*E
#define KENC 320       // F + E
#define KDEC 256       // E (decoder dense composed into Whh)

// Persistent-kernel tiling: 256 CTAs x 128 threads, CTA = 32 batch x 8 e.
// 2 CTAs co-resident per SM; classic placement pairs bid/bid+148 which are
// ALWAYS different batch groups (148 mod 8 = 4) -> barrier waits overlap.
// GEMM: warp w -> (q = w>>1 : K half, rh = w&1 : 16-row half)
//       lane l -> (lg = (l>>3)&3 : 4-row block, le = l&7 : e index)
//       lane computes 4 rows x 4 cols (gates i,f,g,o of e=le), f32x2 col-pairs
#define NCTA 256
#define STH  128
#define GRPS 8         // independent batch groups (32 CTAs each)
#define ASTR 36        // As[k][b] row stride
#define WSTR 36        // Ws[k][c] row stride (32 cols + 4 pad)
#define WSTRP 68       // projection W stride
#define ASTRP 36       // projection A stride

typedef unsigned long long u64;

// ---------------- device scratch (static: no allocation) ----------------
__device__ float g_h[2][EE * BB];                    // hidden state TRANSPOSED [e][b], ping-pong
__device__ float g_Wenc[GG * KENC];                  // [Wih | Whh] rows, K=320
__device__ float g_benc[GG];                         // bih + bhh
__device__ float g_Wdec[GG * KDEC];                  // dWhh + dWih @ Wd
__device__ float g_bdec[GG];                         // dbih + dbhh + dWih @ bd
__device__ float g_WdT[EE * FF];                     // Wd transposed [e][f]
__device__ float g_HallT[(size_t)TT * EE * BB];      // all h_t, TRANSPOSED [t][e][b]
__device__ unsigned g_arrive[GRPS * 32];             // per-group arrive counters
__device__ unsigned g_flag[GRPS * 32];               // per-group generation flags

__device__ __forceinline__ float sigmoidf_(float v) { return 1.0f / (1.0f + __expf(-v)); }
__device__ __forceinline__ float tanhf_(float v) {
    float t = __expf(2.0f * v);
    return 1.0f - 2.0f / (t + 1.0f);
}

// ---- packed f32x2 helpers ----
__device__ __forceinline__ u64 pack2_dup(float a) {
    u64 r; unsigned u = __float_as_uint(a);
    asm("mov.b64 %0, {%1, %2};" : "=l"(r) : "r"(u), "r"(u));
    return r;
}
__device__ __forceinline__ u64 pack2(float x, float y) {
    u64 r;
    asm("mov.b64 %0, {%1, %2};" : "=l"(r) : "r"(__float_as_uint(x)), "r"(__float_as_uint(y)));
    return r;
}
__device__ __forceinline__ void fma2(u64& d, u64 a, u64 b) {
    asm("fma.rn.f32x2 %0, %1, %2, %3;" : "=l"(d) : "l"(a), "l"(b), "l"(d));
}
__device__ __forceinline__ u64 add2(u64 a, u64 b) {
    u64 r;
    asm("add.rn.f32x2 %0, %1, %2;" : "=l"(r) : "l"(a), "l"(b));
    return r;
}
__device__ __forceinline__ float2 unpack2(u64 v) {
    unsigned lo, hi;
    asm("mov.b64 {%0, %1}, %2;" : "=r"(lo), "=r"(hi) : "l"(v));
    float2 r; r.x = __uint_as_float(lo); r.y = __uint_as_float(hi); return r;
}

// ---------------- init ----------------
__global__ void init_state() {
    int i = blockIdx.x * blockDim.x + threadIdx.x;
    if (i < EE * BB) g_h[0][i] = 0.0f;
    if (i < GRPS) { g_arrive[i * 32] = 0; g_flag[i * 32] = 0; }
}

// ---------------- weight packing / decoder composition ----------------
__global__ void pack_weights(const float* __restrict__ eWih, const float* __restrict__ eWhh,
                             const float* __restrict__ ebih, const float* __restrict__ ebhh,
                             const float* __restrict__ dWih, const float* __restrict__ dWhh,
                             const float* __restrict__ dbih, const float* __restrict__ dbhh,
                             const float* __restrict__ Wd,   const float* __restrict__ bd) {
    int row = blockIdx.x;          // 0..1023 (gate row)
    int tid = threadIdx.x;

    for (int k = tid; k < KENC; k += blockDim.x)
        g_Wenc[row * KENC + k] = (k < FF) ? eWih[row * FF + k] : eWhh[row * EE + (k - FF)];

    for (int k = tid; k < KDEC; k += blockDim.x) {
        float s = dWhh[row * EE + k];
        #pragma unroll
        for (int f = 0; f < FF; f++) s += dWih[row * FF + f] * Wd[f * EE + k];
        g_Wdec[row * KDEC + k] = s;
    }
    if (row < EE)
        for (int f = tid; f < FF; f += blockDim.x)
            g_WdT[row * FF + f] = Wd[f * EE + row];
    if (tid == 0) {
        g_benc[row] = ebih[row] + ebhh[row];
        float s = dbih[row] + dbhh[row];
        for (int f = 0; f < FF; f++) s += dWih[row * FF + f] * bd[f];
        g_bdec[row] = s;
    }
}

// ---------------- per-group barrier (32 CTAs): acq_rel atomic + rel/acq flag ----------------
__device__ __forceinline__ void group_sync(unsigned& gen, int grp) {
    __syncthreads();                      // all h stores issued
    if (threadIdx.x == 0) {
        unsigned* arr = &g_arrive[grp * 32];
        unsigned* flg = &g_flag[grp * 32];
        unsigned target = gen + 1;
        unsigned t;
        asm volatile("atom.add.acq_rel.gpu.global.u32 %0, [%1], 1;"
                     : "=r"(t) : "l"(arr) : "memory");
        if (t == 31u) {
            asm volatile("st.relaxed.gpu.global.u32 [%0], %1;" :: "l"(arr), "r"(0u) : "memory");
            asm volatile("st.release.gpu.global.u32 [%0], %1;" :: "l"(flg), "r"(target) : "memory");
        } else {
            unsigned v;
            do {
                asm volatile("ld.acquire.gpu.global.u32 %0, [%1];"
                             : "=r"(v) : "l"(flg) : "memory");
            } while ((int)(v - target) < 0);
        }
    }
    gen++;
    __syncthreads();
}

// ---------------- stage W: Ws[k][c], c = 4*eloc + gate, 32 cols ----------------
template<int K>
__device__ __forceinline__ void stage_W(float* Ws, const float* __restrict__ gW, int e0) {
    int tid  = threadIdx.x;
    int cp   = tid >> 2;                 // 0..31 smem col
    int q    = tid & 3;                  // K quarter
    int gate = cp & 3;
    int eloc = cp >> 2;                  // 0..7
    const float* src = gW + (size_t)(gate * EE + e0 + eloc) * K + q * (K / 4);
    #pragma unroll
    for (int k = 0; k < K / 4; k += 4) {
        float4 v = *(const float4*)(src + k);
        int kk = q * (K / 4) + k;
        Ws[(kk + 0) * WSTR + cp] = v.x;
        Ws[(kk + 1) * WSTR + cp] = v.y;
        Ws[(kk + 2) * WSTR + cp] = v.z;
        Ws[(kk + 3) * WSTR + cp] = v.w;
    }
}

// ---------------- one LSTM step ----------------
template<int K, bool ENC>
__device__ __forceinline__ void do_step(
    const float* __restrict__ Ws, float* __restrict__ As, ulonglong2* __restrict__ scr2,
    const float* __restrict__ x, int t, int rp,
    int b0, int e0, const float4 b4, float2& cc,
    float4* __restrict__ xr,
    int hall_t, unsigned& gen, int grp)
{
    const float* __restrict__ hr = g_h[rp];
    float*       __restrict__ hw = g_h[rp ^ 1];
    const int tid = threadIdx.x;
    const int w   = tid >> 5;
    const int l   = tid & 31;

    // ---- stage A transposed: As[k][b] ----
    if (ENC) {
        // x slice from prefetched registers: thread (b=l, f-chunk=w), 16 f rows
        int f = w * 16;
        #pragma unroll
        for (int j = 0; j < 4; j++) {
            As[(f + 4 * j + 0) * ASTR + l] = xr[j].x;
            As[(f + 4 * j + 1) * ASTR + l] = xr[j].y;
            As[(f + 4 * j + 2) * ASTR + l] = xr[j].z;
            As[(f + 4 * j + 3) * ASTR + l] = xr[j].w;
        }
    }
    const int AOFF = ENC ? FF : 0;
    {
        int bq = (tid & 7) * 4;
        int er = tid >> 3;                   // 0..15
        #pragma unroll
        for (int m = 0; m < 16; m++) {
            int e = er + 16 * m;
            float4 v = __ldcg((const float4*)(hr + e * BB + b0 + bq));
            *(float4*)&As[(AOFF + e) * ASTR + bq] = v;
        }
    }
    __syncthreads();

    // ---- gates GEMM: warp (q = K half, rh = 16-row half); lane (lg 4-row blk, le e) ----
    const int q  = w >> 1, rh = w & 1;
    const int lg = (l >> 3) & 3, le = l & 7;
    const int rb = 16 * rh + 4 * lg;        // CTA-local row base (4 rows)
    const int K2 = K / 2;

    u64 acc[4][2];
    #pragma unroll
    for (int r = 0; r < 4; r++) { acc[r][0] = 0ull; acc[r][1] = 0ull; }

    const float* __restrict__ ap = As + (q * K2) * ASTR + rb;
    const float* __restrict__ wp = Ws + (q * K2) * WSTR + 4 * le;

    #pragma unroll 8
    for (int k = 0; k < K2; k++) {
        float4 av = *(const float4*)(ap);        // rows rb..rb+3
        float4 wv = *(const float4*)(wp);        // (wi,wf,wg,wo) of e=le
        u64 W01 = ((const u64*)&wv)[0];          // (wi,wf) native pair
        u64 W23 = ((const u64*)&wv)[1];          // (wg,wo) native pair
        u64 A0 = pack2_dup(av.x), A1 = pack2_dup(av.y);
        u64 A2 = pack2_dup(av.z), A3 = pack2_dup(av.w);
        fma2(acc[0][0], A0, W01);  fma2(acc[0][1], A0, W23);
        fma2(acc[1][0], A1, W01);  fma2(acc[1][1], A1, W23);
        fma2(acc[2][0], A2, W01);  fma2(acc[2][1], A2, W23);
        fma2(acc[3][0], A3, W01);  fma2(acc[3][1], A3, W23);
        ap += ASTR;  wp += WSTR;
    }

    // ---- symmetric combine: each thread dumps its 2 FOREIGN rows ----
    // q=0 owns rows {rb,rb+1}, dumps acc[2],acc[3]; q=1 owns {rb+2,rb+3}, dumps acc[0],acc[1].
    {
        const int f0 = q ? 0 : 2;
        scr2[tid]       = make_ulonglong2(acc[f0][0],     acc[f0][1]);
        scr2[128 + tid] = make_ulonglong2(acc[f0 + 1][0], acc[f0 + 1][1]);
    }
    __syncthreads();

    // ---- all 4 warps: add partner partials + finalize 2 rows x 1 e ----
    {
        const int o0 = q ? 2 : 0;
        const int pt = tid ^ 64;             // partner thread (other K half)
        ulonglong2 p0 = scr2[pt];
        ulonglong2 p1 = scr2[128 + pt];
        u64 sIF0 = add2(acc[o0][0],     p0.x);
        u64 sGO0 = add2(acc[o0][1],     p0.y);
        u64 sIF1 = add2(acc[o0 + 1][0], p1.x);
        u64 sGO1 = add2(acc[o0 + 1][1], p1.y);

        const int e = e0 + le;
        const int b = b0 + rb + 2 * q;       // this thread's 2 rows
        float2 vi0 = unpack2(sIF0), vg0 = unpack2(sGO0);
        float2 vi1 = unpack2(sIF1), vg1 = unpack2(sGO1);
        float i0 = sigmoidf_(vi0.x + b4.x), f0v = sigmoidf_(vi0.y + b4.y);
        float g0 = tanhf_  (vg0.x + b4.z), o0v = sigmoidf_(vg0.y + b4.w);
        float i1 = sigmoidf_(vi1.x + b4.x), f1v = sigmoidf_(vi1.y + b4.y);
        float g1 = tanhf_  (vg1.x + b4.z), o1v = sigmoidf_(vg1.y + b4.w);
        float c0 = f0v * cc.x + i0 * g0;  cc.x = c0;
        float c1 = f1v * cc.y + i1 * g1;  cc.y = c1;
        float h0 = o0v * tanhf_(c0);
        float h1 = o1v * tanhf_(c1);
        u64 hp = pack2(h0, h1);
        *(u64*)(hw + e * BB + b) = hp;
        if (hall_t >= 0)
            *(u64*)(g_HallT + ((size_t)hall_t * EE + e) * BB + b) = hp;
    }

    // ---- prefetch next x_t while waiting (encoder only) ----
    if (ENC && t + 1 < TT) {
        const float* xs = x + (size_t)(b0 + l) * (TT * FF) + (size_t)(t + 1) * FF + w * 16;
        xr[0] = *(const float4*)(xs);
        xr[1] = *(const float4*)(xs + 4);
        xr[2] = *(const float4*)(xs + 8);
        xr[3] = *(const float4*)(xs + 12);
    }

    group_sync(gen, grp);
}

// ---------------- the persistent recurrence kernel ----------------
__global__ void __launch_bounds__(STH, 2)
persistent_kernel(const float* __restrict__ x)
{
    extern __shared__ float smem[];
    float* Ws = smem;                                    // [K][WSTR]  46,080B
    float* As = smem + KENC * WSTR;                      // [K][ASTR]  46,080B
    ulonglong2* scr2 = (ulonglong2*)(smem + KENC * (WSTR + ASTR));  // 256 ul2 = 4KB

    const int tid = threadIdx.x;
    const int cta = blockIdx.x;              // 0..255
    const int grp = cta & 7;                 // batch group (32 CTAs, independent)
    const int b0  = grp * 32;
    const int e0  = (cta >> 3) * 8;          // 32 e-tiles of 8
    const int eg  = e0 + (tid & 7);
    const int w   = tid >> 5;
    const int l   = tid & 31;

    unsigned gen = 0;
    float2 cc = make_float2(0.f, 0.f);
    float4 xr[4];
    #pragma unroll
    for (int j = 0; j < 4; j++) xr[j] = make_float4(0.f, 0.f, 0.f, 0.f);

    // ===== encoder phase =====
    float4 b4 = make_float4(g_benc[eg], g_benc[EE + eg], g_benc[2 * EE + eg], g_benc[3 * EE + eg]);
    stage_W<KENC>(Ws, g_Wenc, e0);
    {   // prefetch x_0
        const float* xs = x + (size_t)(b0 + l) * (TT * FF) + w * 16;
        xr[0] = *(const float4*)(xs);
        xr[1] = *(const float4*)(xs + 4);
        xr[2] = *(const float4*)(xs + 8);
        xr[3] = *(const float4*)(xs + 12);
    }
    __syncthreads();
    for (int t = 0; t < TT; t++)
        do_step<KENC, true>(Ws, As, scr2, x, t, t & 1, b0, e0, b4, cc, xr,
                            (t == TT - 1) ? 0 : -1, gen, grp);

    // ===== decoder phase (dense projection composed into Whh) =====
    b4 = make_float4(g_bdec[eg], g_bdec[EE + eg], g_bdec[2 * EE + eg], g_bdec[3 * EE + eg]);
    __syncthreads();
    stage_W<KDEC>(Ws, g_Wdec, e0);
    __syncthreads();
    for (int t = 1; t < TT; t++)
        do_step<KDEC, false>(Ws, As, scr2, nullptr, 0, (t - 1) & 1, b0, e0, b4, cc, xr,
                             t, gen, grp);
}

// ---------------- final projection: out[t*B+b][f] = HallT[t][:,b] . WdT[:,f] + bd ----
__global__ void __launch_bounds__(128)
project2(const float* __restrict__ bd, float* __restrict__ out)
{
    extern __shared__ float smem[];
    float* Ws = smem;                        // [256][WSTRP]
    float* As = smem + KDEC * WSTRP;         // [256][ASTRP]

    const int tid = threadIdx.x;
    const int wid = tid >> 5;
    const int lid = tid & 31;
    const int t   = blockIdx.x >> 3;
    const int b0  = (blockIdx.x & 7) * 32;

    #pragma unroll
    for (int j = 0; j < 32; j++) {
        int idx = tid + 128 * j;             // 0..4095
        int e = idx >> 4, fq = (idx & 15) * 4;
        float4 v = *(const float4*)(g_WdT + e * FF + fq);
        *(float4*)&Ws[e * WSTRP + fq] = v;
    }
    {
        int bq = (tid & 7) * 4;
        int er = tid >> 3;
        #pragma unroll
        for (int m = 0; m < 16; m++) {
            int e = er + 16 * m;
            float4 v = *(const float4*)(g_HallT + ((size_t)t * EE + e) * BB + b0 + bq);
            *(float4*)&As[e * ASTRP + bq] = v;
        }
    }
    __syncthreads();

    u64 acc[4][2];
    #pragma unroll
    for (int j = 0; j < 4; j++) { acc[j][0] = 0ull; acc[j][1] = 0ull; }

    const float* __restrict__ arow = As + 8 * wid;
    const float* __restrict__ wrow = Ws + 2 * lid;

    #pragma unroll 4
    for (int k = 0; k < KDEC; k++) {
        float4 a01 = *(const float4*)(arow + k * ASTRP);
        float4 a23 = *(const float4*)(arow + k * ASTRP + 4);
        float2 wv  = *(const float2*)(wrow + k * WSTRP);
        u64 wd0 = pack2_dup(wv.x);
        u64 wd1 = pack2_dup(wv.y);
        u64 A0 = ((const u64*)&a01)[0], A1 = ((const u64*)&a01)[1];
        u64 A2 = ((const u64*)&a23)[0], A3 = ((const u64*)&a23)[1];
        fma2(acc[0][0], A0, wd0);  fma2(acc[0][1], A0, wd1);
        fma2(acc[1][0], A1, wd0);  fma2(acc[1][1], A1, wd1);
        fma2(acc[2][0], A2, wd0);  fma2(acc[2][1], A2, wd1);
        fma2(acc[3][0], A3, wd0);  fma2(acc[3][1], A3, wd1);
    }

    const float bf0 = bd[2 * lid];
    const float bf1 = bd[2 * lid + 1];
    #pragma unroll
    for (int j = 0; j < 4; j++) {
        int r0 = b0 + 8 * wid + 2 * j;
        float2 v0 = unpack2(acc[j][0]);
        float2 v1 = unpack2(acc[j][1]);
        size_t row0 = (size_t)t * BB + r0;
        *(u64*)(out + row0 * FF + 2 * lid)        = pack2(v0.x + bf0, v1.x + bf1);
        *(u64*)(out + (row0 + 1) * FF + 2 * lid)  = pack2(v0.y + bf0, v1.y + bf1);
    }
}

// ---------------- launch ----------------
extern "C" void kernel_launch(void* const* d_in, const int* in_sizes, int n_in,
                              void* d_out, int out_size) {
    const float* x    = (const float*)d_in[0];
    const float* eWih = (const float*)d_in[1];
    const float* eWhh = (const float*)d_in[2];
    const float* ebih = (const float*)d_in[3];
    const float* ebhh = (const float*)d_in[4];
    const float* dWih = (const float*)d_in[5];
    const float* dWhh = (const float*)d_in[6];
    const float* dbih = (const float*)d_in[7];
    const float* dbhh = (const float*)d_in[8];
    const float* Wd   = (const float*)d_in[9];
    const float* bd   = (const float*)d_in[10];
    float* out = (float*)d_out;

    const int smem_main = KENC * (WSTR + ASTR) * (int)sizeof(float) + 256 * (int)sizeof(ulonglong2);
    const int smem_proj = KDEC * (WSTRP + ASTRP) * (int)sizeof(float);
    cudaFuncSetAttribute(persistent_kernel, cudaFuncAttributeMaxDynamicSharedMemorySize, smem_main);
    cudaFuncSetAttribute(project2,          cudaFuncAttributeMaxDynamicSharedMemorySize, smem_proj);

    init_state<<<(EE * BB + 255) / 256, 256>>>();
    pack_weights<<<GG, 256>>>(eWih, eWhh, ebih, ebhh, dWih, dWhh, dbih, dbhh, Wd, bd);
    persistent_kernel<<<NCTA, STH, smem_main>>>(x);
    project2<<<(TT * BB) / 32, 128, smem_proj>>>(bd, out);
}

// round 16
// speedup vs baseline: 1.1230x; 1.1230x over previous
#include <cuda_runtime.h>
#include <math.h>

// Problem dims
#define BB   256
#define TT   1024
#define FF   64
#define EE   256
#define GG   1024      // 4*E
#define KENC 320       // F + E
#define KDEC 256       // E (decoder dense composed into Whh)

// Persistent-kernel tiling: CTA = 32 batch x 16 e-units (64 gate cols), 256 thr
// GEMM: warp w -> (q = w>>2 : K half, rw = w&3 : row octet)
//       lane l -> (lg = l>>4 : 4-row sub-block, le = l&15 : e index)
//       lane computes 4 rows x 4 cols (gates i,f,g,o of e=le), f32x2 col-pairs
// Combine is SYMMETRIC: each thread keeps 2 own rows, dumps 2 foreign rows.
// Barrier is COUNTER-POLL (cumulative, no flag store). x is staged with
// prefetch distance 2 so the post-barrier path is h-LDGs only.
#define NCTA 128
#define STH  256
#define GRPS 8         // independent batch groups (16 CTAs each)
#define ASTR 36        // As[k][b] row stride
#define WSTR 68        // Ws[k][c] row stride
#define WSTRP 68       // projection W stride

typedef unsigned long long u64;

// ---------------- device scratch (static: no allocation) ----------------
__device__ float g_h[2][EE * BB];                    // hidden state TRANSPOSED [e][b], ping-pong
__device__ float g_Wenc[GG * KENC];                  // [Wih | Whh] rows, K=320
__device__ float g_benc[GG];                         // bih + bhh
__device__ float g_Wdec[GG * KDEC];                  // dWhh + dWih @ Wd
__device__ float g_bdec[GG];                         // dbih + dbhh + dWih @ bd
__device__ float g_WdT[EE * FF];                     // Wd transposed [e][f]
__device__ float g_HallT[(size_t)TT * EE * BB];      // all h_t, TRANSPOSED [t][e][b]
__device__ unsigned g_arrive[GRPS * 32];             // per-group CUMULATIVE arrive counters

__device__ __forceinline__ float sigmoidf_(float v) { return 1.0f / (1.0f + __expf(-v)); }
__device__ __forceinline__ float tanhf_(float v) {
    float t = __expf(2.0f * v);
    return 1.0f - 2.0f / (t + 1.0f);
}

// ---- packed f32x2 helpers ----
__device__ __forceinline__ u64 pack2_dup(float a) {
    u64 r; unsigned u = __float_as_uint(a);
    asm("mov.b64 %0, {%1, %2};" : "=l"(r) : "r"(u), "r"(u));
    return r;
}
__device__ __forceinline__ u64 pack2(float x, float y) {
    u64 r;
    asm("mov.b64 %0, {%1, %2};" : "=l"(r) : "r"(__float_as_uint(x)), "r"(__float_as_uint(y)));
    return r;
}
__device__ __forceinline__ void fma2(u64& d, u64 a, u64 b) {
    asm("fma.rn.f32x2 %0, %1, %2, %3;" : "=l"(d) : "l"(a), "l"(b), "l"(d));
}
__device__ __forceinline__ u64 add2(u64 a, u64 b) {
    u64 r;
    asm("add.rn.f32x2 %0, %1, %2;" : "=l"(r) : "l"(a), "l"(b));
    return r;
}
__device__ __forceinline__ float2 unpack2(u64 v) {
    unsigned lo, hi;
    asm("mov.b64 {%0, %1}, %2;" : "=r"(lo), "=r"(hi) : "l"(v));
    float2 r; r.x = __uint_as_float(lo); r.y = __uint_as_float(hi); return r;
}

// ---------------- init ----------------
__global__ void init_state() {
    int i = blockIdx.x * blockDim.x + threadIdx.x;
    if (i < EE * BB) g_h[0][i] = 0.0f;
    if (i < GRPS) g_arrive[i * 32] = 0;
}

// ---------------- weight packing / decoder composition ----------------
__global__ void pack_weights(const float* __restrict__ eWih, const float* __restrict__ eWhh,
                             const float* __restrict__ ebih, const float* __restrict__ ebhh,
                             const float* __restrict__ dWih, const float* __restrict__ dWhh,
                             const float* __restrict__ dbih, const float* __restrict__ dbhh,
                             const float* __restrict__ Wd,   const float* __restrict__ bd) {
    int row = blockIdx.x;          // 0..1023 (gate row)
    int tid = threadIdx.x;

    for (int k = tid; k < KENC; k += blockDim.x)
        g_Wenc[row * KENC + k] = (k < FF) ? eWih[row * FF + k] : eWhh[row * EE + (k - FF)];

    for (int k = tid; k < KDEC; k += blockDim.x) {
        float s = dWhh[row * EE + k];
        #pragma unroll
        for (int f = 0; f < FF; f++) s += dWih[row * FF + f] * Wd[f * EE + k];
        g_Wdec[row * KDEC + k] = s;
    }
    if (row < EE)
        for (int f = tid; f < FF; f += blockDim.x)
            g_WdT[row * FF + f] = Wd[f * EE + row];
    if (tid == 0) {
        g_benc[row] = ebih[row] + ebhh[row];
        float s = dbih[row] + dbhh[row];
        for (int f = 0; f < FF; f++) s += dWih[row * FF + f] * bd[f];
        g_bdec[row] = s;
    }
}

// ---------------- per-group barrier: cumulative counter poll ----------------
// Last arriver's atom.add.acq_rel IS the release; waiters acquire-poll the
// counter itself (no separate flag store on the critical path).
__device__ __forceinline__ void group_sync(unsigned& gen, int grp) {
    __syncthreads();                      // all h stores issued
    gen++;
    if (threadIdx.x == 0) {
        unsigned* arr = &g_arrive[grp * 32];
        unsigned target = gen * 16u;
        unsigned t;
        asm volatile("atom.add.acq_rel.gpu.global.u32 %0, [%1], 1;"
                     : "=r"(t) : "l"(arr) : "memory");
        if (t + 1u != target) {           // not the last arriver -> poll
            unsigned v;
            do {
                asm volatile("ld.acquire.gpu.global.u32 %0, [%1];"
                             : "=r"(v) : "l"(arr) : "memory");
            } while ((int)(v - target) < 0);
        }
    }
    __syncthreads();
}

// ---------------- stage W: Ws[k][c], c = 4*eloc + gate (gates adjacent) ----------------
template<int K>
__device__ __forceinline__ void stage_W(float* Ws, const float* __restrict__ gW, int e0) {
    int tid  = threadIdx.x;
    int cp   = tid >> 2;                 // 0..63 smem col
    int q    = tid & 3;                  // K quarter
    int gate = cp & 3;
    int eloc = cp >> 2;
    const float* src = gW + (size_t)(gate * EE + e0 + eloc) * K + q * (K / 4);
    #pragma unroll
    for (int k = 0; k < K / 4; k += 4) {
        float4 v = *(const float4*)(src + k);
        int kk = q * (K / 4) + k;
        Ws[(kk + 0) * WSTR + cp] = v.x;
        Ws[(kk + 1) * WSTR + cp] = v.y;
        Ws[(kk + 2) * WSTR + cp] = v.z;
        Ws[(kk + 3) * WSTR + cp] = v.w;
    }
}

// ---------------- one LSTM step ----------------
// ENC: As x-region [0,64) was already staged (for THIS t) at the end of the
// previous step; xr holds x_{t+1} in registers. After the combine sync we
// STS x_{t+1} and prefetch x_{t+2} -> post-barrier path is h-LDGs only.
template<int K, bool ENC>
__device__ __forceinline__ void do_step(
    const float* __restrict__ Ws, float* __restrict__ As, ulonglong2* __restrict__ scr2,
    const float* __restrict__ x, int t, int rp,
    int b0, int e0, const float4 b4, float2& cc,
    float4& xr0, float4& xr1,
    int hall_t, unsigned& gen, int grp)
{
    const float* __restrict__ hr = g_h[rp];
    float*       __restrict__ hw = g_h[rp ^ 1];
    const int tid = threadIdx.x;
    const int w   = tid >> 5;
    const int l   = tid & 31;

    // ---- stage A transposed: h only (x already in place) ----
    const int AOFF = ENC ? FF : 0;
    {
        int bq = (tid & 7) * 4;
        int er = tid >> 3;                   // 0..31
        #pragma unroll
        for (int m = 0; m < 8; m++) {
            int e = er + 32 * m;
            float4 v = __ldcg((const float4*)(hr + e * BB + b0 + bq));
            *(float4*)&As[(AOFF + e) * ASTR + bq] = v;
        }
    }
    __syncthreads();

    // ---- gates GEMM: warp (q = K half, rw = row octet); lane (lg 4-row block, le e) ----
    const int q  = w >> 2, rw = w & 3;
    const int lg = l >> 4, le = l & 15;
    const int rb = 8 * rw + 4 * lg;         // CTA-local row base (4 rows)
    const int K2 = K / 2;

    u64 acc[4][2];
    #pragma unroll
    for (int r = 0; r < 4; r++) { acc[r][0] = 0ull; acc[r][1] = 0ull; }

    const float* __restrict__ ap = As + (q * K2) * ASTR + rb;
    const float* __restrict__ wp = Ws + (q * K2) * WSTR + 4 * le;

    #pragma unroll 8
    for (int k = 0; k < K2; k++) {
        float4 av = *(const float4*)(ap);        // rows rb..rb+3 (2-way bcast)
        float4 wv = *(const float4*)(wp);        // (wi,wf,wg,wo) of e=le
        u64 W01 = ((const u64*)&wv)[0];          // (wi,wf) native pair
        u64 W23 = ((const u64*)&wv)[1];          // (wg,wo) native pair
        u64 A0 = pack2_dup(av.x), A1 = pack2_dup(av.y);
        u64 A2 = pack2_dup(av.z), A3 = pack2_dup(av.w);
        fma2(acc[0][0], A0, W01);  fma2(acc[0][1], A0, W23);
        fma2(acc[1][0], A1, W01);  fma2(acc[1][1], A1, W23);
        fma2(acc[2][0], A2, W01);  fma2(acc[2][1], A2, W23);
        fma2(acc[3][0], A3, W01);  fma2(acc[3][1], A3, W23);
        ap += ASTR;  wp += WSTR;
    }

    // ---- symmetric combine: each thread dumps its 2 FOREIGN rows ----
    {
        const int f0 = q ? 0 : 2;
        scr2[tid]       = make_ulonglong2(acc[f0][0],     acc[f0][1]);
        scr2[256 + tid] = make_ulonglong2(acc[f0 + 1][0], acc[f0 + 1][1]);
    }
    __syncthreads();

    // ---- all 8 warps: add partner partials + finalize 2 rows x 1 e ----
    {
        const int o0 = q ? 2 : 0;
        const int pt = tid ^ 128;            // partner thread (other K half)
        ulonglong2 p0 = scr2[pt];
        ulonglong2 p1 = scr2[256 + pt];
        u64 sIF0 = add2(acc[o0][0],     p0.x);
        u64 sGO0 = add2(acc[o0][1],     p0.y);
        u64 sIF1 = add2(acc[o0 + 1][0], p1.x);
        u64 sGO1 = add2(acc[o0 + 1][1], p1.y);

        const int e = e0 + le;
        const int b = b0 + rb + 2 * q;       // this thread's 2 rows
        float2 vi0 = unpack2(sIF0), vg0 = unpack2(sGO0);
        float2 vi1 = unpack2(sIF1), vg1 = unpack2(sGO1);
        float i0 = sigmoidf_(vi0.x + b4.x), f0v = sigmoidf_(vi0.y + b4.y);
        float g0 = tanhf_  (vg0.x + b4.z), o0v = sigmoidf_(vg0.y + b4.w);
        float i1 = sigmoidf_(vi1.x + b4.x), f1v = sigmoidf_(vi1.y + b4.y);
        float g1 = tanhf_  (vg1.x + b4.z), o1v = sigmoidf_(vg1.y + b4.w);
        float c0 = f0v * cc.x + i0 * g0;  cc.x = c0;
        float c1 = f1v * cc.y + i1 * g1;  cc.y = c1;
        float h0 = o0v * tanhf_(c0);
        float h1 = o1v * tanhf_(c1);
        u64 hp = pack2(h0, h1);
        *(u64*)(hw + e * BB + b) = hp;
        if (hall_t >= 0)
            *(u64*)(g_HallT + ((size_t)hall_t * EE + e) * BB + b) = hp;
    }

    // ---- ENC: STS x_{t+1} (regs long-arrived; GEMM reads of As are done),
    //      then prefetch x_{t+2}. Runs in the barrier-wait shadow. ----
    if (ENC) {
        if (t + 1 < TT) {
            int f = w * 8;
            As[(f + 0) * ASTR + l] = xr0.x;  As[(f + 1) * ASTR + l] = xr0.y;
            As[(f + 2) * ASTR + l] = xr0.z;  As[(f + 3) * ASTR + l] = xr0.w;
            As[(f + 4) * ASTR + l] = xr1.x;  As[(f + 5) * ASTR + l] = xr1.y;
            As[(f + 6) * ASTR + l] = xr1.z;  As[(f + 7) * ASTR + l] = xr1.w;
        }
        if (t + 2 < TT) {
            const float* xs = x + (size_t)(b0 + l) * (TT * FF) + (size_t)(t + 2) * FF + w * 8;
            xr0 = *(const float4*)(xs);
            xr1 = *(const float4*)(xs + 4);
        }
    }

    group_sync(gen, grp);
}

// ---------------- the persistent recurrence kernel ----------------
__global__ void __launch_bounds__(STH, 1)
persistent_kernel(const float* __restrict__ x)
{
    extern __shared__ float smem[];
    float* Ws = smem;                                    // [K][WSTR]  87,040B
    float* As = smem + KENC * WSTR;                      // [K][ASTR]  46,080B
    ulonglong2* scr2 = (ulonglong2*)(smem + KENC * (WSTR + ASTR));  // 512 ul2 = 8KB

    const int tid = threadIdx.x;
    const int cta = blockIdx.x;              // 0..127
    const int grp = cta & 7;                 // batch group (independent)
    const int b0  = grp * 32;
    const int e0  = (cta >> 3) * 16;
    const int eg  = e0 + (tid & 15);
    const int w   = tid >> 5;
    const int l   = tid & 31;

    unsigned gen = 0;
    float2 cc = make_float2(0.f, 0.f);
    float4 xr0 = make_float4(0.f, 0.f, 0.f, 0.f);
    float4 xr1 = xr0;

    // ===== encoder phase =====
    float4 b4 = make_float4(g_benc[eg], g_benc[EE + eg], g_benc[2 * EE + eg], g_benc[3 * EE + eg]);
    stage_W<KENC>(Ws, g_Wenc, e0);
    {   // stage x_0 into As, prefetch x_1 into regs
        const float* xs = x + (size_t)(b0 + l) * (TT * FF) + w * 8;
        float4 v0 = *(const float4*)(xs);
        float4 v1 = *(const float4*)(xs + 4);
        int f = w * 8;
        As[(f + 0) * ASTR + l] = v0.x;  As[(f + 1) * ASTR + l] = v0.y;
        As[(f + 2) * ASTR + l] = v0.z;  As[(f + 3) * ASTR + l] = v0.w;
        As[(f + 4) * ASTR + l] = v1.x;  As[(f + 5) * ASTR + l] = v1.y;
        As[(f + 6) * ASTR + l] = v1.z;  As[(f + 7) * ASTR + l] = v1.w;
        const float* xs1 = xs + FF;
        xr0 = *(const float4*)(xs1);
        xr1 = *(const float4*)(xs1 + 4);
    }
    __syncthreads();
    for (int t = 0; t < TT; t++)
        do_step<KENC, true>(Ws, As, scr2, x, t, t & 1, b0, e0, b4, cc, xr0, xr1,
                            (t == TT - 1) ? 0 : -1, gen, grp);

    // ===== decoder phase (dense projection composed into Whh) =====
    b4 = make_float4(g_bdec[eg], g_bdec[EE + eg], g_bdec[2 * EE + eg], g_bdec[3 * EE + eg]);
    __syncthreads();
    stage_W<KDEC>(Ws, g_Wdec, e0);
    __syncthreads();
    for (int t = 1; t < TT; t++)
        do_step<KDEC, false>(Ws, As, scr2, nullptr, 0, (t - 1) & 1, b0, e0, b4, cc, xr0, xr1,
                             t, gen, grp);
}

// ---------------- final projection: out[t*B+b][f] = HallT[t][:,b] . WdT[:,f] + bd ----
__global__ void __launch_bounds__(128)
project2(const float* __restrict__ bd, float* __restrict__ out)
{
    extern __shared__ float smem[];
    float* Ws = smem;                        // [256][WSTRP]
    float* As = smem + KDEC * WSTRP;         // [256][ASTR]

    const int tid = threadIdx.x;
    const int wid = tid >> 5;
    const int lid = tid & 31;
    const int t   = blockIdx.x >> 3;
    const int b0  = (blockIdx.x & 7) * 32;

    #pragma unroll
    for (int j = 0; j < 32; j++) {
        int idx = tid + 128 * j;             // 0..4095
        int e = idx >> 4, fq = (idx & 15) * 4;
        float4 v = *(const float4*)(g_WdT + e * FF + fq);
        *(float4*)&Ws[e * WSTRP + fq] = v;
    }
    {
        int bq = (tid & 7) * 4;
        int er = tid >> 3;
        #pragma unroll
        for (int m = 0; m < 16; m++) {
            int e = er + 16 * m;
            float4 v = *(const float4*)(g_HallT + ((size_t)t * EE + e) * BB + b0 + bq);
            *(float4*)&As[e * ASTR + bq] = v;
        }
    }
    __syncthreads();

    u64 acc[4][2];
    #pragma unroll
    for (int j = 0; j < 4; j++) { acc[j][0] = 0ull; acc[j][1] = 0ull; }

    const float* __restrict__ arow = As + 8 * wid;
    const float* __restrict__ wrow = Ws + 2 * lid;

    #pragma unroll 4
    for (int k = 0; k < KDEC; k++) {
        float4 a01 = *(const float4*)(arow + k * ASTR);
        float4 a23 = *(const float4*)(arow + k * ASTR + 4);
        float2 wv  = *(const float2*)(wrow + k * WSTRP);
        u64 wd0 = pack2_dup(wv.x);
        u64 wd1 = pack2_dup(wv.y);
        u64 A0 = ((const u64*)&a01)[0], A1 = ((const u64*)&a01)[1];
        u64 A2 = ((const u64*)&a23)[0], A3 = ((const u64*)&a23)[1];
        fma2(acc[0][0], A0, wd0);  fma2(acc[0][1], A0, wd1);
        fma2(acc[1][0], A1, wd0);  fma2(acc[1][1], A1, wd1);
        fma2(acc[2][0], A2, wd0);  fma2(acc[2][1], A2, wd1);
        fma2(acc[3][0], A3, wd0);  fma2(acc[3][1], A3, wd1);
    }

    const float bf0 = bd[2 * lid];
    const float bf1 = bd[2 * lid + 1];
    #pragma unroll
    for (int j = 0; j < 4; j++) {
        int r0 = b0 + 8 * wid + 2 * j;
        float2 v0 = unpack2(acc[j][0]);
        float2 v1 = unpack2(acc[j][1]);
        size_t row0 = (size_t)t * BB + r0;
        *(u64*)(out + row0 * FF + 2 * lid)        = pack2(v0.x + bf0, v1.x + bf1);
        *(u64*)(out + (row0 + 1) * FF + 2 * lid)  = pack2(v0.y + bf0, v1.y + bf1);
    }
}

// ---------------- launch ----------------
extern "C" void kernel_launch(void* const* d_in, const int* in_sizes, int n_in,
                              void* d_out, int out_size) {
    const float* x    = (const float*)d_in[0];
    const float* eWih = (const float*)d_in[1];
    const float* eWhh = (const float*)d_in[2];
    const float* ebih = (const float*)d_in[3];
    const float* ebhh = (const float*)d_in[4];
    const float* dWih = (const float*)d_in[5];
    const float* dWhh = (const float*)d_in[6];
    const float* dbih = (const float*)d_in[7];
    const float* dbhh = (const float*)d_in[8];
    const float* Wd   = (const float*)d_in[9];
    const float* bd   = (const float*)d_in[10];
    float* out = (float*)d_out;

    const int smem_main = KENC * (WSTR + ASTR) * (int)sizeof(float) + 512 * (int)sizeof(ulonglong2);
    const int smem_proj = KDEC * (WSTRP + ASTR) * (int)sizeof(float);
    cudaFuncSetAttribute(persistent_kernel, cudaFuncAttributeMaxDynamicSharedMemorySize, smem_main);
    cudaFuncSetAttribute(project2,          cudaFuncAttributeMaxDynamicSharedMemorySize, smem_proj);

    init_state<<<(EE * BB + 255) / 256, 256>>>();
    pack_weights<<<GG, 256>>>(eWih, eWhh, ebih, ebhh, dWih, dWhh, dbih, dbhh, Wd, bd);
    persistent_kernel<<<NCTA, STH, smem_main>>>(x);
    project2<<<(TT * BB) / 32, 128, smem_proj>>>(bd, out);
}